// round 7
// baseline (speedup 1.0000x reference)
#include <cuda_runtime.h>
#include <cuda_bf16.h>
#include <math.h>

// ---------------- problem constants ----------------
#define TT    1024
#define BB    64
#define DIN   17
#define HM    150
#define GM    450       // 3*HM
#define HHD   128
#define GH    384       // 3*HHD
#define MSL   16        // measure length
#define NMEAS 64        // TT/MSL
#define NSEG  4096      // BB*NMEAS
#define HH2   256
#define NP    35
#define NK    15
#define NROW  65536     // TT*BB == MSL*NSEG

// ---------------- scratch (device globals; no allocation) ----------------
__device__ float g_gi_mf[NROW * GM];      // main GRU fwd input gates
__device__ float g_gi_mb[NROW * GM];      // main GRU bwd input gates
__device__ float g_rnn [NROW * 300];      // main biGRU output [t][b][300]
__device__ float g_gi_hf[NROW * GH];      // hier fwd gates [m][n2][384]
__device__ float g_gi_hb[NROW * GH];
__device__ float g_hier[NROW * HH2];      // hier biGRU out [m][n2][256]
__device__ float g_q   [NROW * HH2];
__device__ float g_v   [NROW * HH2];
__device__ float g_ctx [NSEG * HH2];      // [n2][256], n2 = b*64 + s
__device__ float g_part[256 * 4];         // CE partials

// =====================================================================
// General GEMM: C[r][j] = bias[j] + sum_k A[row(r)][k] * W[j][k]
// MODE 0: row(r) = r          (A dense [N][K])
// MODE 1: hier segment remap: r = m*4096+n2, n2=b*64+s  ->  A row (s*16+m)*64+b
// Tile 128x64, 256 threads, 8x4 accumulators per thread, BK=16.
// =====================================================================
#define BKK 16
#define AP  132   // As pitch (floats)
#define WP  68    // Ws pitch

template<int MODE>
__global__ __launch_bounds__(256)
void gemm_kernel(const float* __restrict__ A, const float* __restrict__ W,
                 const float* __restrict__ bias, float* __restrict__ C,
                 int K, int J) {
    __shared__ float As[BKK * AP];
    __shared__ float Ws[BKK * WP];
    const int tid = threadIdx.x;
    const int r0 = blockIdx.y * 128;
    const int j0 = blockIdx.x * 64;
    const int cx = tid & 15;     // 16 groups x 4 cols
    const int cy = tid >> 4;     // 16 groups x 8 rows

    float acc[8][4];
#pragma unroll
    for (int i = 0; i < 8; i++)
#pragma unroll
        for (int j = 0; j < 4; j++) acc[i][j] = 0.f;

    for (int k0 = 0; k0 < K; k0 += BKK) {
        // load A tile (128 rows x 16 k)
#pragma unroll
        for (int i = tid; i < 128 * BKK; i += 256) {
            int rr = i >> 4, kk = i & 15;
            int k = k0 + kk;
            float val = 0.f;
            if (k < K) {
                int r = r0 + rr;
                int arow;
                if (MODE == 0) {
                    arow = r;
                } else {
                    int m = r >> 12, n2 = r & 4095;
                    int b = n2 >> 6, s = n2 & 63;
                    arow = ((s << 4) + m) * 64 + b;
                }
                val = A[(long)arow * K + k];
            }
            As[kk * AP + rr] = val;
        }
        // load W tile (64 j x 16 k)
#pragma unroll
        for (int i = tid; i < 64 * BKK; i += 256) {
            int jj = i >> 4, kk = i & 15;
            int j = j0 + jj, k = k0 + kk;
            Ws[kk * WP + jj] = (k < K && j < J) ? W[(long)j * K + k] : 0.f;
        }
        __syncthreads();
#pragma unroll
        for (int kk = 0; kk < BKK; kk++) {
            const float4 a0 = *(const float4*)&As[kk * AP + cy * 8];
            const float4 a1 = *(const float4*)&As[kk * AP + cy * 8 + 4];
            const float4 bv = *(const float4*)&Ws[kk * WP + cx * 4];
            float ar[8] = {a0.x, a0.y, a0.z, a0.w, a1.x, a1.y, a1.z, a1.w};
            float br[4] = {bv.x, bv.y, bv.z, bv.w};
#pragma unroll
            for (int i = 0; i < 8; i++)
#pragma unroll
                for (int j = 0; j < 4; j++) acc[i][j] += ar[i] * br[j];
        }
        __syncthreads();
    }
#pragma unroll
    for (int i = 0; i < 8; i++) {
        int r = r0 + cy * 8 + i;
#pragma unroll
        for (int j4 = 0; j4 < 4; j4++) {
            int j = j0 + cx * 4 + j4;
            if (j < J) C[(long)r * J + j] = acc[i][j4] + bias[j];
        }
    }
}

// =====================================================================
// Main GRU recurrence: 128 blocks = (dir 2) x (batch 64), 480 threads.
// Whh[450][150]: cols 0..63 in smem (pitch 68), cols 64..149 in registers.
// =====================================================================
__global__ __launch_bounds__(480, 1)
void main_gru_kernel(const float* __restrict__ gi_f, const float* __restrict__ gi_b,
                     const float* __restrict__ Whh_f, const float* __restrict__ Whh_b,
                     const float* __restrict__ bhh_f, const float* __restrict__ bhh_b,
                     float* __restrict__ rnn) {
    extern __shared__ float sm[];
    float* Ws   = sm;                 // 450*68
    float* h_s  = Ws + 450 * 68;      // 160 (150 used)
    float* gh_s = h_s + 160;          // 456 (450 used)

    const int tid = threadIdx.x;
    const int dir = blockIdx.x >> 6;
    const int b   = blockIdx.x & 63;
    const float* Whh = dir ? Whh_b : Whh_f;
    const float* bhh = dir ? bhh_b : bhh_f;
    const float* gi  = dir ? gi_b  : gi_f;

    for (int i = tid; i < 450 * 64; i += 480) {
        int g = i >> 6, k = i & 63;
        Ws[g * 68 + k] = Whh[g * 150 + k];
    }
    const int g = tid;
    float wreg[86];
    float bh = 0.f;
    if (g < 450) {
        bh = bhh[g];
#pragma unroll
        for (int i = 0; i < 86; i++) wreg[i] = Whh[g * 150 + 64 + i];
    }
    for (int i = tid; i < 160; i += 480) h_s[i] = 0.f;
    __syncthreads();

    for (int step = 0; step < TT; step++) {
        const int t = dir ? (TT - 1 - step) : step;
        if (g < 450) {
            float acc = bh;
#pragma unroll
            for (int k = 0; k < 64; k += 4) {
                float4 w  = *(const float4*)&Ws[g * 68 + k];
                float4 h4 = *(const float4*)&h_s[k];
                acc += w.x * h4.x + w.y * h4.y + w.z * h4.z + w.w * h4.w;
            }
#pragma unroll
            for (int i = 0; i < 84; i += 4) {
                float4 h4 = *(const float4*)&h_s[64 + i];
                acc += wreg[i] * h4.x + wreg[i + 1] * h4.y
                     + wreg[i + 2] * h4.z + wreg[i + 3] * h4.w;
            }
            acc += wreg[84] * h_s[148] + wreg[85] * h_s[149];
            gh_s[g] = acc;
        }
        __syncthreads();
        if (g < 150) {
            const long base = ((long)t * 64 + b) * GM;
            float gir = gi[base + g];
            float giz = gi[base + 150 + g];
            float gin = gi[base + 300 + g];
            float r = 1.f / (1.f + expf(-(gir + gh_s[g])));
            float z = 1.f / (1.f + expf(-(giz + gh_s[150 + g])));
            float n = tanhf(gin + r * gh_s[300 + g]);
            float hn = (1.f - z) * n + z * h_s[g];
            h_s[g] = hn;
            rnn[((long)t * 64 + b) * 300 + dir * 150 + g] = hn;
        }
        __syncthreads();
    }
}

// =====================================================================
// Hier GRU: 1024 blocks = (dir 2) x (512 chain-groups), 8 chains/block,
// 384 threads. Whh[384][128] fully in smem (pitch 132, conflict-free f4).
// =====================================================================
#define HPITCH 132
__global__ __launch_bounds__(384, 1)
void hier_gru_kernel(const float* __restrict__ gi_f, const float* __restrict__ gi_b,
                     const float* __restrict__ Whh_f, const float* __restrict__ Whh_b,
                     const float* __restrict__ bhh_f, const float* __restrict__ bhh_b,
                     float* __restrict__ hier) {
    extern __shared__ float sm[];
    float* Ws   = sm;                    // 384*132
    float* h_s  = Ws + 384 * HPITCH;     // 8*128
    float* gh_s = h_s + 8 * 128;         // 8*384

    const int tid = threadIdx.x;
    const int dir = blockIdx.x >> 9;
    const int n2base = (blockIdx.x & 511) * 8;
    const float* Whh = dir ? Whh_b : Whh_f;
    const float* bhh = dir ? bhh_b : bhh_f;
    const float* gi  = dir ? gi_b  : gi_f;

    for (int i = tid; i < 384 * 128; i += 384) {
        int gg = i >> 7, k = i & 127;
        Ws[gg * HPITCH + k] = Whh[gg * 128 + k];
    }
    for (int i = tid; i < 8 * 128; i += 384) h_s[i] = 0.f;
    const int g = tid;
    const float bh = bhh[g];
    __syncthreads();

    for (int step = 0; step < MSL; step++) {
        const int m = dir ? (MSL - 1 - step) : step;
        float acc[8];
#pragma unroll
        for (int c = 0; c < 8; c++) acc[c] = bh;
#pragma unroll 8
        for (int k = 0; k < 128; k += 4) {
            float4 w = *(const float4*)&Ws[g * HPITCH + k];
#pragma unroll
            for (int c = 0; c < 8; c++) {
                float4 h4 = *(const float4*)&h_s[c * 128 + k];
                acc[c] += w.x * h4.x + w.y * h4.y + w.z * h4.z + w.w * h4.w;
            }
        }
#pragma unroll
        for (int c = 0; c < 8; c++) gh_s[c * 384 + g] = acc[c];
        __syncthreads();
        for (int idx = tid; idx < 1024; idx += 384) {
            int c = idx >> 7, j = idx & 127;
            int n2 = n2base + c;
            long base = ((long)m * NSEG + n2) * GH;
            float gir = gi[base + j];
            float giz = gi[base + 128 + j];
            float gin = gi[base + 256 + j];
            float r = 1.f / (1.f + expf(-(gir + gh_s[c * 384 + j])));
            float z = 1.f / (1.f + expf(-(giz + gh_s[c * 384 + 128 + j])));
            float n = tanhf(gin + r * gh_s[c * 384 + 256 + j]);
            float hn = (1.f - z) * n + z * h_s[c * 128 + j];
            h_s[c * 128 + j] = hn;
            hier[((long)m * NSEG + n2) * HH2 + dir * 128 + j] = hn;
        }
        __syncthreads();
    }
}

// =====================================================================
// Attention per segment: scores = q@v^T (16x16), softmax over m,
// w[m] = sum_l attn[l][m], ctx = w @ hv. 4096 blocks x 256 threads.
// =====================================================================
#define APITCH 261
__global__ __launch_bounds__(256)
void attn_kernel(const float* __restrict__ q, const float* __restrict__ v,
                 const float* __restrict__ hv, float* __restrict__ ctx) {
    extern __shared__ float sm[];
    float* qs = sm;
    float* vs = qs + 16 * APITCH;
    float* hs = vs + 16 * APITCH;
    float* ss = hs + 16 * APITCH;    // 16*17 scores / probs
    float* ws = ss + 16 * 17;        // 16

    const int tid = threadIdx.x;
    const int n2 = blockIdx.x;

    for (int i = tid; i < 16 * 256; i += 256) {
        int m = i >> 8, d = i & 255;
        long src = ((long)m * NSEG + n2) * HH2 + d;
        qs[m * APITCH + d] = q[src];
        vs[m * APITCH + d] = v[src];
        hs[m * APITCH + d] = hv[src];
    }
    __syncthreads();
    {
        int l = tid >> 4, mm = tid & 15;
        float acc = 0.f;
#pragma unroll 8
        for (int k = 0; k < 256; k++) acc += qs[l * APITCH + k] * vs[mm * APITCH + k];
        ss[l * 17 + mm] = acc;
    }
    __syncthreads();
    if (tid < 16) {
        int l = tid;
        float mx = -1e30f;
#pragma unroll
        for (int mm = 0; mm < 16; mm++) mx = fmaxf(mx, ss[l * 17 + mm]);
        float s = 0.f;
        float e[16];
#pragma unroll
        for (int mm = 0; mm < 16; mm++) { e[mm] = expf(ss[l * 17 + mm] - mx); s += e[mm]; }
        float inv = 1.f / s;
#pragma unroll
        for (int mm = 0; mm < 16; mm++) ss[l * 17 + mm] = e[mm] * inv;
    }
    __syncthreads();
    if (tid < 16) {
        int mm = tid;
        float s = 0.f;
#pragma unroll
        for (int l = 0; l < 16; l++) s += ss[l * 17 + mm];
        ws[mm] = s;
    }
    __syncthreads();
    {
        int d = tid;
        float acc = 0.f;
#pragma unroll
        for (int mm = 0; mm < 16; mm++) acc += ws[mm] * hs[mm * APITCH + d];
        ctx[(long)n2 * HH2 + d] = acc;
    }
}

// =====================================================================
// Fused output logits + masked CE. One thread per row; Wp/Wk in smem
// (broadcast reads). Per-block partial sums -> g_part.
// =====================================================================
__global__ __launch_bounds__(256, 1)
void ce_kernel(const float* __restrict__ rnn, const float* __restrict__ ctx,
               const float* __restrict__ Wp, const float* __restrict__ bp,
               const float* __restrict__ Wk, const float* __restrict__ bk,
               const int* __restrict__ pitches, const int* __restrict__ kss,
               float* __restrict__ part) {
    extern __shared__ float sm[];
    float* Wps = sm;                   // 35*556
    float* Wks = Wps + NP * 556;       // 15*256
    float* bps = Wks + NK * 256;       // 35
    float* bks = bps + NP;             // 15
    float* red = bks + NK;             // 256*4

    const int tid = threadIdx.x;
    for (int i = tid; i < NP * 556; i += 256) Wps[i] = Wp[i];
    for (int i = tid; i < NK * 256; i += 256) Wks[i] = Wk[i];
    if (tid < NP) bps[tid] = bp[tid];
    if (tid < NK) bks[tid] = bk[tid];
    __syncthreads();

    const int row = blockIdx.x * 256 + tid;   // t*64 + b
    const int t = row >> 6, b = row & 63;
    const int mi = t >> 4;
    const float* xr = rnn + (long)row * 300;
    const float* xc = ctx + ((long)(b * 64 + mi)) * HH2;

    float lg[NP], lgk[NK];
#pragma unroll
    for (int c = 0; c < NP; c++) lg[c] = bps[c];
#pragma unroll
    for (int c = 0; c < NK; c++) lgk[c] = bks[c];

    for (int k = 0; k < 300; k++) {
        float x = xr[k];
#pragma unroll
        for (int c = 0; c < NP; c++) lg[c] += Wps[c * 556 + k] * x;
    }
    for (int k = 0; k < 256; k++) {
        float x = xc[k];
#pragma unroll
        for (int c = 0; c < NP; c++) lg[c] += Wps[c * 556 + 300 + k] * x;
#pragma unroll
        for (int c = 0; c < NK; c++) lgk[c] += Wks[c * 256 + k] * x;
    }

    // pitch CE (pad 34)
    int tp = pitches[row];
    float mx = -1e30f;
#pragma unroll
    for (int c = 0; c < NP; c++) mx = fmaxf(mx, lg[c]);
    float s = 0.f;
#pragma unroll
    for (int c = 0; c < NP; c++) s += expf(lg[c] - mx);
    float lsel = 0.f;
#pragma unroll
    for (int c = 0; c < NP; c++) lsel += (c == tp) ? lg[c] : 0.f;
    float nllp = 0.f, cp = 0.f;
    if (tp != 34) { nllp = (logf(s) + mx) - lsel; cp = 1.f; }

    // ks CE (pad 14)
    int tk = kss[row];
    float mxk = -1e30f;
#pragma unroll
    for (int c = 0; c < NK; c++) mxk = fmaxf(mxk, lgk[c]);
    float sk = 0.f;
#pragma unroll
    for (int c = 0; c < NK; c++) sk += expf(lgk[c] - mxk);
    float ksel = 0.f;
#pragma unroll
    for (int c = 0; c < NK; c++) ksel += (c == tk) ? lgk[c] : 0.f;
    float nllk = 0.f, ck = 0.f;
    if (tk != 14) { nllk = (logf(sk) + mxk) - ksel; ck = 1.f; }

    red[tid] = nllp; red[256 + tid] = cp; red[512 + tid] = nllk; red[768 + tid] = ck;
    __syncthreads();
    for (int off = 128; off > 0; off >>= 1) {
        if (tid < off) {
            red[tid]       += red[tid + off];
            red[256 + tid] += red[256 + tid + off];
            red[512 + tid] += red[512 + tid + off];
            red[768 + tid] += red[768 + tid + off];
        }
        __syncthreads();
    }
    if (tid == 0) {
        part[blockIdx.x * 4 + 0] = red[0];
        part[blockIdx.x * 4 + 1] = red[256];
        part[blockIdx.x * 4 + 2] = red[512];
        part[blockIdx.x * 4 + 3] = red[768];
    }
}

__global__ __launch_bounds__(256)
void final_kernel(const float* __restrict__ part, float* __restrict__ out) {
    __shared__ float s0[256], s1[256], s2[256], s3[256];
    const int tid = threadIdx.x;
    s0[tid] = part[tid * 4 + 0];
    s1[tid] = part[tid * 4 + 1];
    s2[tid] = part[tid * 4 + 2];
    s3[tid] = part[tid * 4 + 3];
    __syncthreads();
    for (int off = 128; off > 0; off >>= 1) {
        if (tid < off) {
            s0[tid] += s0[tid + off]; s1[tid] += s1[tid + off];
            s2[tid] += s2[tid + off]; s3[tid] += s3[tid + off];
        }
        __syncthreads();
    }
    if (tid == 0)
        out[0] = s0[0] / fmaxf(s1[0], 1.f) + s2[0] / fmaxf(s3[0], 1.f);
}

// =====================================================================
// host
// =====================================================================
extern "C" void kernel_launch(void* const* d_in, const int* in_sizes, int n_in,
                              void* d_out, int out_size) {
    const float* sentences = (const float*)d_in[0];
    const int*   pitches   = (const int*)d_in[1];
    const int*   kss       = (const int*)d_in[2];
    // d_in[3] sentences_len, d_in[4] eoM: structural constants, unused
    const float* mWih_f = (const float*)d_in[5];
    const float* mWhh_f = (const float*)d_in[6];
    const float* mbih_f = (const float*)d_in[7];
    const float* mbhh_f = (const float*)d_in[8];
    const float* mWih_b = (const float*)d_in[9];
    const float* mWhh_b = (const float*)d_in[10];
    const float* mbih_b = (const float*)d_in[11];
    const float* mbhh_b = (const float*)d_in[12];
    const float* hWih_f = (const float*)d_in[13];
    const float* hWhh_f = (const float*)d_in[14];
    const float* hbih_f = (const float*)d_in[15];
    const float* hbhh_f = (const float*)d_in[16];
    const float* hWih_b = (const float*)d_in[17];
    const float* hWhh_b = (const float*)d_in[18];
    const float* hbih_b = (const float*)d_in[19];
    const float* hbhh_b = (const float*)d_in[20];
    const float* Wq = (const float*)d_in[21];
    const float* bq = (const float*)d_in[22];
    const float* Wv = (const float*)d_in[23];
    const float* bv = (const float*)d_in[24];
    const float* Wp = (const float*)d_in[25];
    const float* bp = (const float*)d_in[26];
    const float* Wk = (const float*)d_in[27];
    const float* bk = (const float*)d_in[28];
    float* out = (float*)d_out;

    float *p_gi_mf, *p_gi_mb, *p_rnn, *p_gi_hf, *p_gi_hb, *p_hier, *p_q, *p_v, *p_ctx, *p_part;
    cudaGetSymbolAddress((void**)&p_gi_mf, g_gi_mf);
    cudaGetSymbolAddress((void**)&p_gi_mb, g_gi_mb);
    cudaGetSymbolAddress((void**)&p_rnn,   g_rnn);
    cudaGetSymbolAddress((void**)&p_gi_hf, g_gi_hf);
    cudaGetSymbolAddress((void**)&p_gi_hb, g_gi_hb);
    cudaGetSymbolAddress((void**)&p_hier,  g_hier);
    cudaGetSymbolAddress((void**)&p_q,     g_q);
    cudaGetSymbolAddress((void**)&p_v,     g_v);
    cudaGetSymbolAddress((void**)&p_ctx,   g_ctx);
    cudaGetSymbolAddress((void**)&p_part,  g_part);

    // opt-in smem sizes
    const int SM_MAIN = (450 * 68 + 160 + 456) * 4;                 // 124,864
    const int SM_HIER = (384 * HPITCH + 8 * 128 + 8 * 384) * 4;     // 219,136
    const int SM_ATTN = (3 * 16 * APITCH + 16 * 17 + 16) * 4;       // 51,264
    const int SM_CE   = (NP * 556 + NK * 256 + NP + NK + 1024) * 4; // 97,496
    cudaFuncSetAttribute(main_gru_kernel, cudaFuncAttributeMaxDynamicSharedMemorySize, SM_MAIN);
    cudaFuncSetAttribute(hier_gru_kernel, cudaFuncAttributeMaxDynamicSharedMemorySize, SM_HIER);
    cudaFuncSetAttribute(attn_kernel,     cudaFuncAttributeMaxDynamicSharedMemorySize, SM_ATTN);
    cudaFuncSetAttribute(ce_kernel,       cudaFuncAttributeMaxDynamicSharedMemorySize, SM_CE);

    dim3 thr(256);
    // 1-2. main input-side gates: [65536,17] @ [17,450]^T
    gemm_kernel<0><<<dim3((GM + 63) / 64, NROW / 128), thr>>>(sentences, mWih_f, mbih_f, p_gi_mf, DIN, GM);
    gemm_kernel<0><<<dim3((GM + 63) / 64, NROW / 128), thr>>>(sentences, mWih_b, mbih_b, p_gi_mb, DIN, GM);
    // 3. main bi-GRU recurrence
    main_gru_kernel<<<128, 480, SM_MAIN>>>(p_gi_mf, p_gi_mb, mWhh_f, mWhh_b, mbhh_f, mbhh_b, p_rnn);
    // 4-5. hier input-side gates (segment-remapped rows): [65536,300] @ [300,384]^T
    gemm_kernel<1><<<dim3(GH / 64, NROW / 128), thr>>>(p_rnn, hWih_f, hbih_f, p_gi_hf, 300, GH);
    gemm_kernel<1><<<dim3(GH / 64, NROW / 128), thr>>>(p_rnn, hWih_b, hbih_b, p_gi_hb, 300, GH);
    // 6. hier bi-GRU
    hier_gru_kernel<<<1024, 384, SM_HIER>>>(p_gi_hf, p_gi_hb, hWhh_f, hWhh_b, hbhh_f, hbhh_b, p_hier);
    // 7-8. q, v projections: [65536,256] @ [256,256]^T
    gemm_kernel<0><<<dim3(HH2 / 64, NROW / 128), thr>>>(p_hier, Wq, bq, p_q, HH2, HH2);
    gemm_kernel<0><<<dim3(HH2 / 64, NROW / 128), thr>>>(p_hier, Wv, bv, p_v, HH2, HH2);
    // 9. attention + context
    attn_kernel<<<NSEG, 256, SM_ATTN>>>(p_q, p_v, p_hier, p_ctx);
    // 10. fused logits + CE partials
    ce_kernel<<<NROW / 256, 256, SM_CE>>>(p_rnn, p_ctx, Wp, bp, Wk, bk, pitches, kss, p_part);
    // 11. final reduce -> loss
    final_kernel<<<1, 256>>>(p_part, out);
}

// round 8
// speedup vs baseline: 1.2012x; 1.2012x over previous
#include <cuda_runtime.h>
#include <cuda_bf16.h>
#include <math.h>

// ---------------- problem constants ----------------
#define TT    1024
#define BB    64
#define DIN   17
#define HM    150
#define GM    450       // 3*HM
#define HHD   128
#define GH    384       // 3*HHD
#define MSL   16        // measure length
#define NMEAS 64        // TT/MSL
#define NSEG  4096      // BB*NMEAS
#define HH2   256
#define NP    35
#define NK    15
#define NROW  65536     // TT*BB == MSL*NSEG

typedef unsigned long long u64;

// packed fp32x2 FMA (sm_103a): d = a*b + d, lanewise on (lo,hi)
#define FMA2(d, a, b) asm("fma.rn.f32x2 %0, %1, %2, %0;" : "+l"(d) : "l"(a), "l"(b))
// replicate one fp32 into both lanes of a pair
#define PACKR(p, f) asm("mov.b64 %0, {%1, %1};" : "=l"(p) : "r"(__float_as_uint(f)))

__device__ __forceinline__ float pair_lo(u64 p) { return __uint_as_float((unsigned)p); }
__device__ __forceinline__ float pair_hi(u64 p) { return __uint_as_float((unsigned)(p >> 32)); }
__device__ __forceinline__ u64 d2u_lo(double2 d) { return (u64)__double_as_longlong(d.x); }
__device__ __forceinline__ u64 d2u_hi(double2 d) { return (u64)__double_as_longlong(d.y); }

// ---------------- scratch (device globals; no allocation) ----------------
__device__ float g_gi_mf[NROW * GM];
__device__ float g_gi_mb[NROW * GM];
__device__ float g_rnn [NROW * 300];
__device__ float g_gi_hf[NROW * GH];
__device__ float g_gi_hb[NROW * GH];
__device__ float g_hier[NROW * HH2];
__device__ float g_q   [NROW * HH2];
__device__ float g_v   [NROW * HH2];
__device__ float g_ctx [NSEG * HH2];
__device__ float g_part[256 * 4];

// =====================================================================
// GEMM v2: C[r][j] = bias[j] + sum_k A[row(r)][k] * W[j][k]
// Tile 128x128, 256 threads, 8x8 per thread as 4x8 packed f32x2 accs.
// MODE 0: row(r) = r;  MODE 1: hier segment remap.
// =====================================================================
template<int MODE>
__global__ __launch_bounds__(256)
void gemm_kernel(const float* __restrict__ A, const float* __restrict__ W,
                 const float* __restrict__ bias, float* __restrict__ C,
                 int K, int J) {
    __shared__ __align__(16) float As[8 * 132];   // [k][row]
    __shared__ __align__(16) float Ws[8 * 132];   // [k][col]
    const int tid = threadIdx.x;
    const int r0 = blockIdx.y * 128;
    const int j0 = blockIdx.x * 128;
    const int cx = tid & 15;     // col group: cols {cx*4+q, 64+cx*4+q}
    const int cy = tid >> 4;     // row group: rows cy*8 .. cy*8+7

    u64 acc[4][8];
#pragma unroll
    for (int i = 0; i < 4; i++)
#pragma unroll
        for (int j = 0; j < 8; j++) acc[i][j] = 0ull;

    // loader: thread covers one row (lrow), 4 consecutive k (lk..lk+3)
    const int lrow = tid >> 1;
    const int lk   = (tid & 1) * 4;
    int arow;
    {
        int r = r0 + lrow;
        if (MODE == 0) arow = r;
        else { int m = r >> 12, n2 = r & 4095; int b = n2 >> 6, s = n2 & 63;
               arow = ((s << 4) + m) * 64 + b; }
    }
    const float* Arow = A + (long)arow * K;
    const int wj = j0 + lrow;
    const bool wvalid = (wj < J);
    const float* Wrow = W + (long)(wvalid ? wj : 0) * K;

    for (int k0 = 0; k0 < K; k0 += 8) {
#pragma unroll
        for (int q = 0; q < 4; q++) {
            int k = k0 + lk + q;
            As[(lk + q) * 132 + lrow] = (k < K) ? Arow[k] : 0.f;
            Ws[(lk + q) * 132 + lrow] = (wvalid && k < K) ? Wrow[k] : 0.f;
        }
        __syncthreads();
#pragma unroll
        for (int kk = 0; kk < 8; kk++) {
            double2 a0 = *(const double2*)&As[kk * 132 + cy * 8];
            double2 a1 = *(const double2*)&As[kk * 132 + cy * 8 + 4];
            u64 ap[4] = { d2u_lo(a0), d2u_hi(a0), d2u_lo(a1), d2u_hi(a1) };
            float4 w0 = *(const float4*)&Ws[kk * 132 + cx * 4];
            float4 w1 = *(const float4*)&Ws[kk * 132 + 64 + cx * 4];
            u64 wp[8];
            PACKR(wp[0], w0.x); PACKR(wp[1], w0.y); PACKR(wp[2], w0.z); PACKR(wp[3], w0.w);
            PACKR(wp[4], w1.x); PACKR(wp[5], w1.y); PACKR(wp[6], w1.z); PACKR(wp[7], w1.w);
#pragma unroll
            for (int ip = 0; ip < 4; ip++)
#pragma unroll
                for (int j = 0; j < 8; j++)
                    FMA2(acc[ip][j], ap[ip], wp[j]);
        }
        __syncthreads();
    }
    // epilogue: acc[ip][j] holds rows (cy*8+2ip, cy*8+2ip+1), col group j
#pragma unroll
    for (int ip = 0; ip < 4; ip++) {
        long ra = r0 + cy * 8 + 2 * ip;
#pragma unroll
        for (int j = 0; j < 8; j++) {
            int j_ = j0 + ((j < 4) ? (cx * 4 + j) : (64 + cx * 4 + (j - 4)));
            if (j_ < J) {
                float bb = bias[j_];
                C[ra * J + j_]       = pair_lo(acc[ip][j]) + bb;
                C[(ra + 1) * J + j_] = pair_hi(acc[ip][j]) + bb;
            }
        }
    }
}

// =====================================================================
// Main GRU recurrence: 128 blocks = (dir 2) x (batch 64), 480 threads.
// Whh[450][150]: cols 0..63 in smem (pitch 68), cols 64..149 in reg pairs.
// gi prefetched into registers before the matvec (hides DRAM latency).
// =====================================================================
__global__ __launch_bounds__(480, 1)
void main_gru_kernel(const float* __restrict__ gi_f, const float* __restrict__ gi_b,
                     const float* __restrict__ Whh_f, const float* __restrict__ Whh_b,
                     const float* __restrict__ bhh_f, const float* __restrict__ bhh_b,
                     float* __restrict__ rnn) {
    extern __shared__ __align__(16) float sm[];
    float* Ws   = sm;                 // 450*68
    float* h_s  = Ws + 450 * 68;      // 160 (150 used)
    float* gh_s = h_s + 160;          // 456 (450 used)

    const int tid = threadIdx.x;
    const int dir = blockIdx.x >> 6;
    const int b   = blockIdx.x & 63;
    const float* Whh = dir ? Whh_b : Whh_f;
    const float* bhh = dir ? bhh_b : bhh_f;
    const float* gi  = dir ? gi_b  : gi_f;

    for (int i = tid; i < 450 * 64; i += 480) {
        int g2 = i >> 6, k = i & 63;
        Ws[g2 * 68 + k] = Whh[g2 * 150 + k];
    }
    const int g = tid;
    u64 wp[43];          // col pairs (64+2i, 65+2i)
    float bh = 0.f;
    if (g < 450) {
        bh = bhh[g];
#pragma unroll
        for (int i = 0; i < 43; i++)
            wp[i] = *(const u64*)&Whh[g * 150 + 64 + 2 * i];
    }
    for (int i = tid; i < 160; i += 480) h_s[i] = 0.f;
    __syncthreads();

    for (int step = 0; step < TT; step++) {
        const int t = dir ? (TT - 1 - step) : step;
        // prefetch gi for this step (consumed after the barrier)
        float gir = 0.f, giz = 0.f, gin = 0.f;
        const long base = ((long)t * 64 + b) * GM;
        if (g < 150) {
            gir = gi[base + g];
            giz = gi[base + 150 + g];
            gin = gi[base + 300 + g];
        }
        if (g < 450) {
            u64 accp = 0ull;
#pragma unroll
            for (int k = 0; k < 64; k += 4) {
                double2 w2 = *(const double2*)&Ws[g * 68 + k];
                double2 h2 = *(const double2*)&h_s[k];
                FMA2(accp, d2u_lo(w2), d2u_lo(h2));
                FMA2(accp, d2u_hi(w2), d2u_hi(h2));
            }
#pragma unroll
            for (int q = 0; q < 21; q++) {
                double2 h2 = *(const double2*)&h_s[64 + 4 * q];
                FMA2(accp, wp[2 * q], d2u_lo(h2));
                FMA2(accp, wp[2 * q + 1], d2u_hi(h2));
            }
            {
                u64 hl = *(const u64*)&h_s[148];
                FMA2(accp, wp[42], hl);
            }
            gh_s[g] = pair_lo(accp) + pair_hi(accp) + bh;
        }
        __syncthreads();
        if (g < 150) {
            float r = 1.f / (1.f + expf(-(gir + gh_s[g])));
            float z = 1.f / (1.f + expf(-(giz + gh_s[150 + g])));
            float n = tanhf(gin + r * gh_s[300 + g]);
            float hn = (1.f - z) * n + z * h_s[g];
            h_s[g] = hn;
            rnn[((long)t * 64 + b) * 300 + dir * 150 + g] = hn;
        }
        __syncthreads();
    }
}

// =====================================================================
// Hier GRU: 1024 blocks = (dir 2) x (512 chain-groups), 8 chains/block,
// 384 threads. Whh[384][128] in smem (pitch 132). f32x2 matvec + gi prefetch.
// =====================================================================
#define HPITCH 132
__global__ __launch_bounds__(384, 1)
void hier_gru_kernel(const float* __restrict__ gi_f, const float* __restrict__ gi_b,
                     const float* __restrict__ Whh_f, const float* __restrict__ Whh_b,
                     const float* __restrict__ bhh_f, const float* __restrict__ bhh_b,
                     float* __restrict__ hier) {
    extern __shared__ __align__(16) float sm[];
    float* Ws   = sm;                    // 384*132
    float* h_s  = Ws + 384 * HPITCH;     // 8*128
    float* gh_s = h_s + 8 * 128;         // 8*384

    const int tid = threadIdx.x;
    const int dir = blockIdx.x >> 9;
    const int n2base = (blockIdx.x & 511) * 8;
    const float* Whh = dir ? Whh_b : Whh_f;
    const float* bhh = dir ? bhh_b : bhh_f;
    const float* gi  = dir ? gi_b  : gi_f;

    for (int i = tid; i < 384 * 128; i += 384) {
        int gg = i >> 7, k = i & 127;
        Ws[gg * HPITCH + k] = Whh[gg * 128 + k];
    }
    for (int i = tid; i < 8 * 128; i += 384) h_s[i] = 0.f;
    const int g = tid;
    const float bh = bhh[g];
    __syncthreads();

    for (int step = 0; step < MSL; step++) {
        const int m = dir ? (MSL - 1 - step) : step;
        // prefetch gi for the (up to 3) update slots this thread owns
        float pg[3][3];
#pragma unroll
        for (int ii = 0; ii < 3; ii++) {
            int idx = tid + ii * 384;
            if (idx < 1024) {
                int c = idx >> 7, j = idx & 127;
                long gb = ((long)m * NSEG + (n2base + c)) * GH;
                pg[ii][0] = gi[gb + j];
                pg[ii][1] = gi[gb + 128 + j];
                pg[ii][2] = gi[gb + 256 + j];
            }
        }
        // matvec for all 8 chains
        u64 accp[8];
#pragma unroll
        for (int c = 0; c < 8; c++) accp[c] = 0ull;
#pragma unroll 8
        for (int k = 0; k < 128; k += 4) {
            double2 w2 = *(const double2*)&Ws[g * HPITCH + k];
            u64 wlo = d2u_lo(w2), whi = d2u_hi(w2);
#pragma unroll
            for (int c = 0; c < 8; c++) {
                double2 h2 = *(const double2*)&h_s[c * 128 + k];
                FMA2(accp[c], wlo, d2u_lo(h2));
                FMA2(accp[c], whi, d2u_hi(h2));
            }
        }
#pragma unroll
        for (int c = 0; c < 8; c++)
            gh_s[c * 384 + g] = pair_lo(accp[c]) + pair_hi(accp[c]) + bh;
        __syncthreads();
#pragma unroll
        for (int ii = 0; ii < 3; ii++) {
            int idx = tid + ii * 384;
            if (idx < 1024) {
                int c = idx >> 7, j = idx & 127;
                int n2 = n2base + c;
                float r = 1.f / (1.f + expf(-(pg[ii][0] + gh_s[c * 384 + j])));
                float z = 1.f / (1.f + expf(-(pg[ii][1] + gh_s[c * 384 + 128 + j])));
                float n = tanhf(pg[ii][2] + r * gh_s[c * 384 + 256 + j]);
                float hn = (1.f - z) * n + z * h_s[c * 128 + j];
                h_s[c * 128 + j] = hn;
                hier[((long)m * NSEG + n2) * HH2 + dir * 128 + j] = hn;
            }
        }
        __syncthreads();
    }
}

// =====================================================================
// Attention per segment (unchanged; not a bottleneck).
// =====================================================================
#define APITCH 261
__global__ __launch_bounds__(256)
void attn_kernel(const float* __restrict__ q, const float* __restrict__ v,
                 const float* __restrict__ hv, float* __restrict__ ctx) {
    extern __shared__ float smA[];
    float* qs = smA;
    float* vs = qs + 16 * APITCH;
    float* hs = vs + 16 * APITCH;
    float* ss = hs + 16 * APITCH;
    float* ws = ss + 16 * 17;

    const int tid = threadIdx.x;
    const int n2 = blockIdx.x;

    for (int i = tid; i < 16 * 256; i += 256) {
        int m = i >> 8, d = i & 255;
        long src = ((long)m * NSEG + n2) * HH2 + d;
        qs[m * APITCH + d] = q[src];
        vs[m * APITCH + d] = v[src];
        hs[m * APITCH + d] = hv[src];
    }
    __syncthreads();
    {
        int l = tid >> 4, mm = tid & 15;
        float acc = 0.f;
#pragma unroll 8
        for (int k = 0; k < 256; k++) acc += qs[l * APITCH + k] * vs[mm * APITCH + k];
        ss[l * 17 + mm] = acc;
    }
    __syncthreads();
    if (tid < 16) {
        int l = tid;
        float mx = -1e30f;
#pragma unroll
        for (int mm = 0; mm < 16; mm++) mx = fmaxf(mx, ss[l * 17 + mm]);
        float s = 0.f;
        float e[16];
#pragma unroll
        for (int mm = 0; mm < 16; mm++) { e[mm] = expf(ss[l * 17 + mm] - mx); s += e[mm]; }
        float inv = 1.f / s;
#pragma unroll
        for (int mm = 0; mm < 16; mm++) ss[l * 17 + mm] = e[mm] * inv;
    }
    __syncthreads();
    if (tid < 16) {
        int mm = tid;
        float s = 0.f;
#pragma unroll
        for (int l = 0; l < 16; l++) s += ss[l * 17 + mm];
        ws[mm] = s;
    }
    __syncthreads();
    {
        int d = tid;
        float acc = 0.f;
#pragma unroll
        for (int mm = 0; mm < 16; mm++) acc += ws[mm] * hs[mm * APITCH + d];
        ctx[(long)n2 * HH2 + d] = acc;
    }
}

// =====================================================================
// Fused output logits + masked CE; float4 activation loads.
// =====================================================================
__global__ __launch_bounds__(256, 1)
void ce_kernel(const float* __restrict__ rnn, const float* __restrict__ ctx,
               const float* __restrict__ Wp, const float* __restrict__ bp,
               const float* __restrict__ Wk, const float* __restrict__ bk,
               const int* __restrict__ pitches, const int* __restrict__ kss,
               float* __restrict__ part) {
    extern __shared__ __align__(16) float smC[];
    float* Wps = smC;                  // 35*556
    float* Wks = Wps + NP * 556;       // 15*256
    float* bps = Wks + NK * 256;       // 35
    float* bks = bps + NP;             // 15
    float* red = bks + NK;             // 256*4

    const int tid = threadIdx.x;
    for (int i = tid; i < NP * 556; i += 256) Wps[i] = Wp[i];
    for (int i = tid; i < NK * 256; i += 256) Wks[i] = Wk[i];
    if (tid < NP) bps[tid] = bp[tid];
    if (tid < NK) bks[tid] = bk[tid];
    __syncthreads();

    const int row = blockIdx.x * 256 + tid;
    const int t = row >> 6, b = row & 63;
    const int mi = t >> 4;
    const float* xr = rnn + (long)row * 300;
    const float* xc = ctx + ((long)(b * 64 + mi)) * HH2;

    float lg[NP], lgk[NK];
#pragma unroll
    for (int c = 0; c < NP; c++) lg[c] = bps[c];
#pragma unroll
    for (int c = 0; c < NK; c++) lgk[c] = bks[c];

    for (int k4 = 0; k4 < 75; k4++) {
        float4 x = *(const float4*)&xr[k4 * 4];
        const float* wrow = &Wps[k4 * 4];
#pragma unroll
        for (int c = 0; c < NP; c++) {
            const float* wr = wrow + c * 556;
            lg[c] += wr[0] * x.x + wr[1] * x.y + wr[2] * x.z + wr[3] * x.w;
        }
    }
    for (int k4 = 0; k4 < 64; k4++) {
        float4 x = *(const float4*)&xc[k4 * 4];
#pragma unroll
        for (int c = 0; c < NP; c++) {
            const float* wr = &Wps[c * 556 + 300 + k4 * 4];
            lg[c] += wr[0] * x.x + wr[1] * x.y + wr[2] * x.z + wr[3] * x.w;
        }
#pragma unroll
        for (int c = 0; c < NK; c++) {
            const float* wr = &Wks[c * 256 + k4 * 4];
            lgk[c] += wr[0] * x.x + wr[1] * x.y + wr[2] * x.z + wr[3] * x.w;
        }
    }

    int tp = pitches[row];
    float mx = -1e30f;
#pragma unroll
    for (int c = 0; c < NP; c++) mx = fmaxf(mx, lg[c]);
    float s = 0.f;
#pragma unroll
    for (int c = 0; c < NP; c++) s += expf(lg[c] - mx);
    float lsel = 0.f;
#pragma unroll
    for (int c = 0; c < NP; c++) lsel += (c == tp) ? lg[c] : 0.f;
    float nllp = 0.f, cp = 0.f;
    if (tp != 34) { nllp = (logf(s) + mx) - lsel; cp = 1.f; }

    int tk = kss[row];
    float mxk = -1e30f;
#pragma unroll
    for (int c = 0; c < NK; c++) mxk = fmaxf(mxk, lgk[c]);
    float sk = 0.f;
#pragma unroll
    for (int c = 0; c < NK; c++) sk += expf(lgk[c] - mxk);
    float ksel = 0.f;
#pragma unroll
    for (int c = 0; c < NK; c++) ksel += (c == tk) ? lgk[c] : 0.f;
    float nllk = 0.f, ck = 0.f;
    if (tk != 14) { nllk = (logf(sk) + mxk) - ksel; ck = 1.f; }

    red[tid] = nllp; red[256 + tid] = cp; red[512 + tid] = nllk; red[768 + tid] = ck;
    __syncthreads();
    for (int off = 128; off > 0; off >>= 1) {
        if (tid < off) {
            red[tid]       += red[tid + off];
            red[256 + tid] += red[256 + tid + off];
            red[512 + tid] += red[512 + tid + off];
            red[768 + tid] += red[768 + tid + off];
        }
        __syncthreads();
    }
    if (tid == 0) {
        part[blockIdx.x * 4 + 0] = red[0];
        part[blockIdx.x * 4 + 1] = red[256];
        part[blockIdx.x * 4 + 2] = red[512];
        part[blockIdx.x * 4 + 3] = red[768];
    }
}

__global__ __launch_bounds__(256)
void final_kernel(const float* __restrict__ part, float* __restrict__ out) {
    __shared__ float s0[256], s1[256], s2[256], s3[256];
    const int tid = threadIdx.x;
    s0[tid] = part[tid * 4 + 0];
    s1[tid] = part[tid * 4 + 1];
    s2[tid] = part[tid * 4 + 2];
    s3[tid] = part[tid * 4 + 3];
    __syncthreads();
    for (int off = 128; off > 0; off >>= 1) {
        if (tid < off) {
            s0[tid] += s0[tid + off]; s1[tid] += s1[tid + off];
            s2[tid] += s2[tid + off]; s3[tid] += s3[tid + off];
        }
        __syncthreads();
    }
    if (tid == 0)
        out[0] = s0[0] / fmaxf(s1[0], 1.f) + s2[0] / fmaxf(s3[0], 1.f);
}

// =====================================================================
// host
// =====================================================================
extern "C" void kernel_launch(void* const* d_in, const int* in_sizes, int n_in,
                              void* d_out, int out_size) {
    const float* sentences = (const float*)d_in[0];
    const int*   pitches   = (const int*)d_in[1];
    const int*   kss       = (const int*)d_in[2];
    const float* mWih_f = (const float*)d_in[5];
    const float* mWhh_f = (const float*)d_in[6];
    const float* mbih_f = (const float*)d_in[7];
    const float* mbhh_f = (const float*)d_in[8];
    const float* mWih_b = (const float*)d_in[9];
    const float* mWhh_b = (const float*)d_in[10];
    const float* mbih_b = (const float*)d_in[11];
    const float* mbhh_b = (const float*)d_in[12];
    const float* hWih_f = (const float*)d_in[13];
    const float* hWhh_f = (const float*)d_in[14];
    const float* hbih_f = (const float*)d_in[15];
    const float* hbhh_f = (const float*)d_in[16];
    const float* hWih_b = (const float*)d_in[17];
    const float* hWhh_b = (const float*)d_in[18];
    const float* hbih_b = (const float*)d_in[19];
    const float* hbhh_b = (const float*)d_in[20];
    const float* Wq = (const float*)d_in[21];
    const float* bq = (const float*)d_in[22];
    const float* Wv = (const float*)d_in[23];
    const float* bv = (const float*)d_in[24];
    const float* Wp = (const float*)d_in[25];
    const float* bp = (const float*)d_in[26];
    const float* Wk = (const float*)d_in[27];
    const float* bk = (const float*)d_in[28];
    float* out = (float*)d_out;

    float *p_gi_mf, *p_gi_mb, *p_rnn, *p_gi_hf, *p_gi_hb, *p_hier, *p_q, *p_v, *p_ctx, *p_part;
    cudaGetSymbolAddress((void**)&p_gi_mf, g_gi_mf);
    cudaGetSymbolAddress((void**)&p_gi_mb, g_gi_mb);
    cudaGetSymbolAddress((void**)&p_rnn,   g_rnn);
    cudaGetSymbolAddress((void**)&p_gi_hf, g_gi_hf);
    cudaGetSymbolAddress((void**)&p_gi_hb, g_gi_hb);
    cudaGetSymbolAddress((void**)&p_hier,  g_hier);
    cudaGetSymbolAddress((void**)&p_q,     g_q);
    cudaGetSymbolAddress((void**)&p_v,     g_v);
    cudaGetSymbolAddress((void**)&p_ctx,   g_ctx);
    cudaGetSymbolAddress((void**)&p_part,  g_part);

    const int SM_MAIN = (450 * 68 + 160 + 456) * 4;
    const int SM_HIER = (384 * HPITCH + 8 * 128 + 8 * 384) * 4;
    const int SM_ATTN = (3 * 16 * APITCH + 16 * 17 + 16) * 4;
    const int SM_CE   = (NP * 556 + NK * 256 + NP + NK + 1024) * 4;
    cudaFuncSetAttribute(main_gru_kernel, cudaFuncAttributeMaxDynamicSharedMemorySize, SM_MAIN);
    cudaFuncSetAttribute(hier_gru_kernel, cudaFuncAttributeMaxDynamicSharedMemorySize, SM_HIER);
    cudaFuncSetAttribute(attn_kernel,     cudaFuncAttributeMaxDynamicSharedMemorySize, SM_ATTN);
    cudaFuncSetAttribute(ce_kernel,       cudaFuncAttributeMaxDynamicSharedMemorySize, SM_CE);

    dim3 thr(256);
    // main input-side gates: [65536,17] @ [17,450]^T
    gemm_kernel<0><<<dim3((GM + 127) / 128, NROW / 128), thr>>>(sentences, mWih_f, mbih_f, p_gi_mf, DIN, GM);
    gemm_kernel<0><<<dim3((GM + 127) / 128, NROW / 128), thr>>>(sentences, mWih_b, mbih_b, p_gi_mb, DIN, GM);
    // main bi-GRU recurrence
    main_gru_kernel<<<128, 480, SM_MAIN>>>(p_gi_mf, p_gi_mb, mWhh_f, mWhh_b, mbhh_f, mbhh_b, p_rnn);
    // hier input-side gates (segment-remapped rows): [65536,300] @ [300,384]^T
    gemm_kernel<1><<<dim3(GH / 128, NROW / 128), thr>>>(p_rnn, hWih_f, hbih_f, p_gi_hf, 300, GH);
    gemm_kernel<1><<<dim3(GH / 128, NROW / 128), thr>>>(p_rnn, hWih_b, hbih_b, p_gi_hb, 300, GH);
    // hier bi-GRU
    hier_gru_kernel<<<1024, 384, SM_HIER>>>(p_gi_hf, p_gi_hb, hWhh_f, hWhh_b, hbhh_f, hbhh_b, p_hier);
    // q, v projections: [65536,256] @ [256,256]^T
    gemm_kernel<0><<<dim3(HH2 / 128, NROW / 128), thr>>>(p_hier, Wq, bq, p_q, HH2, HH2);
    gemm_kernel<0><<<dim3(HH2 / 128, NROW / 128), thr>>>(p_hier, Wv, bv, p_v, HH2, HH2);
    // attention + context
    attn_kernel<<<NSEG, 256, SM_ATTN>>>(p_q, p_v, p_hier, p_ctx);
    // fused logits + CE partials
    ce_kernel<<<NROW / 256, 256, SM_CE>>>(p_rnn, p_ctx, Wp, bp, Wk, bk, pitches, kss, p_part);
    // final reduce -> loss
    final_kernel<<<1, 256>>>(p_part, out);
}